// round 10
// baseline (speedup 1.0000x reference)
#include <cuda_runtime.h>
#include <cfloat>
#include <climits>

#define VOCAB 30522
#define CAND_CAP (1 << 20)
#define OVF_CAP  (1 << 18)
#define TOPK 10
#define NB1 296
#define STAGE_CAP 2048

// ---- device scratch (BSS zero-init; every launch restores the invariant) ----
__device__ float g_scores[500000];
__device__ int   g_cand_doc[CAND_CAP];
__device__ int   g_ncand;          // reset by topk2
__device__ int   g_ovf_pos[OVF_CAP];
__device__ float g_ovf_val[OVF_CAP];
__device__ int   g_novf;           // reset by topk2
__device__ int   g_done;           // CTA-completion ticket, reset by topk2
__device__ float g_blk_v[NB1 * TOPK];
__device__ int   g_blk_i[NB1 * TOPK];

// ---------------------------------------------------------------------------
// score_fused: stream nnz (4x-batched int4). BRANCHLESS two-level filter:
//   1) 1024-bit bloom in 32 smem words (one per bank -> conflict-free LDS)
//   2) qtab LDS with CLAMPED index: failing lanes read qtab[0] (broadcast),
//      passing lanes (~1/warp) read their own word. No divergence, ~1-2
//      wavefronts per element. Only the true-hit branch remains (~3%/warp).
// CTA-local hit staging + per-CTA resolve; tiny global spill on overflow,
// resolved by the last-finishing CTA.
// ---------------------------------------------------------------------------
__global__ void __launch_bounds__(1024, 1)
score_kernel(const int* __restrict__ qidx, const float* __restrict__ qval, int qn,
             const int* __restrict__ indice, const float* __restrict__ values,
             const int* __restrict__ crow, int n_docs, int nnz)
{
    extern __shared__ float qtab[];   // VOCAB floats = 122088 B
    __shared__ unsigned s_bloom[32];  // 1024-bit filter: one word per bank
    __shared__ int   sc_cnt;
    __shared__ int   sc_pos[STAGE_CAP];
    __shared__ float sc_val[STAGE_CAP];
    __shared__ int   cd_cnt;
    __shared__ int   cd_doc[STAGE_CAP];
    __shared__ int   cd_base, cd_flush;
    __shared__ int   s_last;

    for (int i = threadIdx.x; i < VOCAB; i += 1024) qtab[i] = 0.0f;
    if (threadIdx.x < 32) s_bloom[threadIdx.x] = 0u;
    if (threadIdx.x == 0) { sc_cnt = 0; cd_cnt = 0; }
    __syncthreads();
    if (threadIdx.x < qn) {
        int e = qidx[threadIdx.x];
        atomicAdd(&qtab[e], qval[threadIdx.x]);
        atomicOr(&s_bloom[(e >> 5) & 31], 1u << (e & 31));
    }
    __syncthreads();

    const int gtid = blockIdx.x * 1024 + threadIdx.x;
    const int gsz  = gridDim.x * 1024;
    const int total4 = nnz >> 2;
    const int4* __restrict__ ind4 = (const int4*)indice;

    // branchless filter; rare true-hit branch only
    #define EMIT(e, jj)                                                        \
        {                                                                      \
            unsigned w = s_bloom[((e) >> 5) & 31];                             \
            bool pass = (w >> ((e) & 31)) & 1u;                                \
            int idx = pass ? (e) : 0;                                          \
            float qraw = qtab[idx];                                            \
            float q = pass ? qraw : 0.0f;                                      \
            if (q != 0.0f) {                                                   \
                float v = q * __ldg(values + (jj));                            \
                int p = atomicAdd(&sc_cnt, 1);                                 \
                if (p < STAGE_CAP) { sc_pos[p] = (jj); sc_val[p] = v; }        \
                else {                                                         \
                    int gp = atomicAdd(&g_novf, 1);                            \
                    if (gp < OVF_CAP) {                                        \
                        g_ovf_pos[gp] = (jj); g_ovf_val[gp] = v;               \
                    }                                                          \
                }                                                              \
            }                                                                  \
        }

    int i = gtid;
    for (; i + 3 * gsz < total4; i += 4 * gsz) {
        int4 a = __ldcs(ind4 + i);
        int4 b = __ldcs(ind4 + i + gsz);
        int4 c = __ldcs(ind4 + i + 2 * gsz);
        int4 d = __ldcs(ind4 + i + 3 * gsz);

        int ja = i << 2, jb = (i + gsz) << 2, jc = (i + 2 * gsz) << 2, jd = (i + 3 * gsz) << 2;
        EMIT(a.x, ja)     EMIT(a.y, ja + 1) EMIT(a.z, ja + 2) EMIT(a.w, ja + 3)
        EMIT(b.x, jb)     EMIT(b.y, jb + 1) EMIT(b.z, jb + 2) EMIT(b.w, jb + 3)
        EMIT(c.x, jc)     EMIT(c.y, jc + 1) EMIT(c.z, jc + 2) EMIT(c.w, jc + 3)
        EMIT(d.x, jd)     EMIT(d.y, jd + 1) EMIT(d.z, jd + 2) EMIT(d.w, jd + 3)
    }
    for (; i < total4; i += gsz) {
        int4 a = __ldcs(ind4 + i);
        int j = i << 2;
        EMIT(a.x, j) EMIT(a.y, j + 1) EMIT(a.z, j + 2) EMIT(a.w, j + 3)
    }
    int jt = (total4 << 2) + gtid;
    if (jt < nnz) {
        int e = indice[jt];
        EMIT(e, jt)
    }
    #undef EMIT

    // ---- per-CTA resolve of staged hits (parallel binary searches) ----
    __syncthreads();
    int nh = sc_cnt; if (nh > STAGE_CAP) nh = STAGE_CAP;
    for (int t = threadIdx.x; t < nh; t += 1024) {
        int j = sc_pos[t];
        int lo = 0, hi = n_docs;
        while (lo < hi) {
            int mid = (lo + hi + 1) >> 1;
            if (crow[mid] <= j) lo = mid; else hi = mid - 1;
        }
        float old = atomicAdd(&g_scores[lo], sc_val[t]);
        if (old == 0.0f) {
            int p = atomicAdd(&cd_cnt, 1);
            if (p < STAGE_CAP) cd_doc[p] = lo;
            else {
                int gp = atomicAdd(&g_ncand, 1);
                if (gp < CAND_CAP) g_cand_doc[gp] = lo;
            }
        }
    }

    // ---- flush candidates: ONE global atomic per CTA ----
    __syncthreads();
    if (threadIdx.x == 0) {
        int c = cd_cnt; if (c > STAGE_CAP) c = STAGE_CAP;
        int base = atomicAdd(&g_ncand, c);
        if (base + c > CAND_CAP) c = (base < CAND_CAP) ? (CAND_CAP - base) : 0;
        cd_base = base; cd_flush = c;
    }
    __syncthreads();
    for (int t = threadIdx.x; t < cd_flush; t += 1024)
        g_cand_doc[cd_base + t] = cd_doc[t];

    // ---- last-finishing CTA resolves the (rare) overflow spill ----
    __threadfence();
    if (threadIdx.x == 0)
        s_last = (atomicAdd(&g_done, 1) == gridDim.x - 1) ? 1 : 0;
    __syncthreads();
    if (s_last) {
        int no = g_novf; if (no > OVF_CAP) no = OVF_CAP;
        for (int t = threadIdx.x; t < no; t += 1024) {
            int j = g_ovf_pos[t];
            int lo = 0, hi = n_docs;
            while (lo < hi) {
                int mid = (lo + hi + 1) >> 1;
                if (crow[mid] <= j) lo = mid; else hi = mid - 1;
            }
            float old = atomicAdd(&g_scores[lo], g_ovf_val[t]);
            if (old == 0.0f) {
                int gp = atomicAdd(&g_ncand, 1);
                if (gp < CAND_CAP) g_cand_doc[gp] = lo;
            }
        }
    }
}

// ---------------------------------------------------------------------------
// top-k helpers (static register indexing only)
// ---------------------------------------------------------------------------
__device__ __forceinline__ void insert10(float* lv, int* li, float s, int d) {
    if (s > lv[TOPK - 1] || (s == lv[TOPK - 1] && d < li[TOPK - 1])) {
        lv[TOPK - 1] = s; li[TOPK - 1] = d;
        #pragma unroll
        for (int k = TOPK - 1; k > 0; k--) {
            bool sw = (lv[k] > lv[k - 1]) ||
                      (lv[k] == lv[k - 1] && li[k] < li[k - 1]);
            if (sw) {
                float tv = lv[k]; lv[k] = lv[k - 1]; lv[k - 1] = tv;
                int   ti = li[k]; li[k] = li[k - 1]; li[k - 1] = ti;
            }
        }
    }
}

__device__ __forceinline__ void warp_merge10(float* lv, int* li,
                                             float* out_v, int* out_i) {
    int lane = threadIdx.x & 31;
    #pragma unroll
    for (int r = 0; r < TOPK; r++) {
        float bv = lv[0]; int bi = li[0]; int bl = lane;
        #pragma unroll
        for (int off = 16; off; off >>= 1) {
            float ov = __shfl_down_sync(0xffffffffu, bv, off);
            int   oi = __shfl_down_sync(0xffffffffu, bi, off);
            int   ol = __shfl_down_sync(0xffffffffu, bl, off);
            if (ov > bv || (ov == bv && oi < bi)) { bv = ov; bi = oi; bl = ol; }
        }
        bl = __shfl_sync(0xffffffffu, bl, 0);
        float wv = __shfl_sync(0xffffffffu, bv, 0);
        int   wi = __shfl_sync(0xffffffffu, bi, 0);
        if (lane == bl) {
            #pragma unroll
            for (int k = 0; k < TOPK - 1; k++) { lv[k] = lv[k + 1]; li[k] = li[k + 1]; }
            lv[TOPK - 1] = -FLT_MAX; li[TOPK - 1] = INT_MAX;
        }
        if (lane == 0) { out_v[r] = wv; out_i[r] = wi; }
    }
}

__device__ __forceinline__ void block_merge10(const float* sv, const int* si,
                                              int nwarp, float* out_v, int* out_i) {
    int lane = threadIdx.x & 31;
    float lv[TOPK]; int li[TOPK];
    #pragma unroll
    for (int k = 0; k < TOPK; k++) {
        if (lane < nwarp) { lv[k] = sv[lane * TOPK + k]; li[k] = si[lane * TOPK + k]; }
        else              { lv[k] = -FLT_MAX;            li[k] = INT_MAX;            }
    }
    warp_merge10(lv, li, out_v, out_i);
}

// ---------------------------------------------------------------------------
// top-k pass 1: scan candidates (batched gathers, MLP=4) AND zero each
// candidate score after reading it (fused cleanup -> restores invariant)
// ---------------------------------------------------------------------------
__global__ void __launch_bounds__(256)
topk1_kernel() {
    float lv[TOPK]; int li[TOPK];
    #pragma unroll
    for (int k = 0; k < TOPK; k++) { lv[k] = -FLT_MAX; li[k] = INT_MAX; }

    int nc = g_ncand;
    if (nc > CAND_CAP) nc = CAND_CAP;
    int gtid = blockIdx.x * blockDim.x + threadIdx.x;
    int gsz  = gridDim.x * blockDim.x;

    int t = gtid;
    for (; t + 3 * gsz < nc; t += 4 * gsz) {
        int d0 = g_cand_doc[t];
        int d1 = g_cand_doc[t + gsz];
        int d2 = g_cand_doc[t + 2 * gsz];
        int d3 = g_cand_doc[t + 3 * gsz];
        float s0 = g_scores[d0];
        float s1 = g_scores[d1];
        float s2 = g_scores[d2];
        float s3 = g_scores[d3];
        g_scores[d0] = 0.0f;
        g_scores[d1] = 0.0f;
        g_scores[d2] = 0.0f;
        g_scores[d3] = 0.0f;
        insert10(lv, li, s0, d0);
        insert10(lv, li, s1, d1);
        insert10(lv, li, s2, d2);
        insert10(lv, li, s3, d3);
    }
    for (; t < nc; t += gsz) {
        int d = g_cand_doc[t];
        float s = g_scores[d];
        g_scores[d] = 0.0f;
        insert10(lv, li, s, d);
    }

    __shared__ float sv[8 * TOPK];
    __shared__ int   si[8 * TOPK];
    int wid = threadIdx.x >> 5;
    warp_merge10(lv, li, sv + wid * TOPK, si + wid * TOPK);
    __syncthreads();
    if (wid == 0)
        block_merge10(sv, si, 8, g_blk_v + blockIdx.x * TOPK,
                      g_blk_i + blockIdx.x * TOPK);
}

// ---------------------------------------------------------------------------
// top-k pass 2: merge NB1*TOPK block winners, write output, reset counters
// out layout: [TOPK values][TOPK indices-as-float]
// ---------------------------------------------------------------------------
__global__ void __launch_bounds__(256)
topk2_kernel(float* __restrict__ out, int out_size) {
    const int NC = NB1 * TOPK;
    float lv[TOPK]; int li[TOPK];
    #pragma unroll
    for (int k = 0; k < TOPK; k++) { lv[k] = -FLT_MAX; li[k] = INT_MAX; }

    for (int p = threadIdx.x; p < NC; p += 256)
        insert10(lv, li, g_blk_v[p], g_blk_i[p]);

    __shared__ float sv[8 * TOPK];
    __shared__ int   si[8 * TOPK];
    __shared__ float fv[TOPK];
    __shared__ int   fi[TOPK];
    int wid = threadIdx.x >> 5;
    warp_merge10(lv, li, sv + wid * TOPK, si + wid * TOPK);
    __syncthreads();
    if (wid == 0) block_merge10(sv, si, 8, fv, fi);
    __syncthreads();

    if (threadIdx.x < TOPK) {
        int k = threadIdx.x;
        if (k < out_size) out[k] = fv[k];
        if (TOPK + k < out_size) out[TOPK + k] = (float)fi[k];
    }
    if (threadIdx.x == 0) {   // reset all counters for next graph replay
        g_ncand = 0;
        g_novf = 0;
        g_done = 0;
    }
}

// ---------------------------------------------------------------------------
// kernel_launch
// Inputs: q_indices(i32,32) q_values(f32,32) crow(i32,N+1) indice(i32,nnz)
//         values(f32,nnz) [top_k]
// ---------------------------------------------------------------------------
extern "C" void kernel_launch(void* const* d_in, const int* in_sizes, int n_in,
                              void* d_out, int out_size) {
    const int*   qidx   = (const int*)d_in[0];
    const float* qval   = (const float*)d_in[1];
    const int*   crow   = (const int*)d_in[2];
    const int*   indice = (const int*)d_in[3];
    const float* values = (const float*)d_in[4];

    int qn     = in_sizes[0];
    int n_docs = in_sizes[2] - 1;
    int nnz    = in_sizes[3];

    const int SMEM_Q = VOCAB * (int)sizeof(float);
    cudaFuncSetAttribute(score_kernel, cudaFuncAttributeMaxDynamicSharedMemorySize, SMEM_Q);

    score_kernel<<<148, 1024, SMEM_Q>>>(qidx, qval, qn, indice, values,
                                        crow, n_docs, nnz);
    topk1_kernel<<<NB1, 256>>>();
    topk2_kernel<<<1, 256>>>((float*)d_out, out_size);
}

// round 11
// speedup vs baseline: 1.1835x; 1.1835x over previous
#include <cuda_runtime.h>
#include <cfloat>
#include <climits>

#define VOCAB 30522
#define CAND_CAP (1 << 20)
#define OVF_CAP  (1 << 18)
#define TOPK 10
#define NB1 296
#define STAGE_CAP 2048

// ---- device scratch (BSS zero-init; every launch restores the invariant) ----
__device__ float g_scores[500000];
__device__ int   g_cand_doc[CAND_CAP];
__device__ int   g_ncand;          // reset by topk2
__device__ int   g_ovf_pos[OVF_CAP];
__device__ float g_ovf_val[OVF_CAP];
__device__ int   g_novf;           // reset by topk2
__device__ int   g_done;           // CTA-completion ticket, reset by topk2
__device__ float g_blk_v[NB1 * TOPK];
__device__ int   g_blk_i[NB1 * TOPK];

// ---------------------------------------------------------------------------
// score_fused: stream nnz (4x-batched int4 -> MLP>=4), PLAIN smem qtab lookup
// (LDS + FSETP + rare branch: minimal issue count; LDS wavefronts overlap the
// DRAM stream). CTA-local hit staging + per-CTA resolve (binary search on
// L2-resident crow + scatter-add + candidate staging). Tiny global spill on
// staging overflow, resolved by the last-finishing CTA.
// ---------------------------------------------------------------------------
__global__ void __launch_bounds__(1024, 1)
score_kernel(const int* __restrict__ qidx, const float* __restrict__ qval, int qn,
             const int* __restrict__ indice, const float* __restrict__ values,
             const int* __restrict__ crow, int n_docs, int nnz)
{
    extern __shared__ float qtab[];   // VOCAB floats = 122088 B
    __shared__ int   sc_cnt;
    __shared__ int   sc_pos[STAGE_CAP];
    __shared__ float sc_val[STAGE_CAP];
    __shared__ int   cd_cnt;
    __shared__ int   cd_doc[STAGE_CAP];
    __shared__ int   cd_base, cd_flush;
    __shared__ int   s_last;

    for (int i = threadIdx.x; i < VOCAB; i += 1024) qtab[i] = 0.0f;
    if (threadIdx.x == 0) { sc_cnt = 0; cd_cnt = 0; }
    __syncthreads();
    if (threadIdx.x < qn) atomicAdd(&qtab[qidx[threadIdx.x]], qval[threadIdx.x]);
    __syncthreads();

    const int gtid = blockIdx.x * 1024 + threadIdx.x;
    const int gsz  = gridDim.x * 1024;
    const int total4 = nnz >> 2;
    const int4* __restrict__ ind4 = (const int4*)indice;

    // minimal hot path: 1 LDS + 1 FSETP + rarely-taken branch per element
    #define EMIT(e, jj)                                                        \
        {                                                                      \
            float q = qtab[e];                                                 \
            if (q != 0.0f) {                                                   \
                float v = q * __ldg(values + (jj));                            \
                int p = atomicAdd(&sc_cnt, 1);                                 \
                if (p < STAGE_CAP) { sc_pos[p] = (jj); sc_val[p] = v; }        \
                else {                                                         \
                    int gp = atomicAdd(&g_novf, 1);                            \
                    if (gp < OVF_CAP) {                                        \
                        g_ovf_pos[gp] = (jj); g_ovf_val[gp] = v;               \
                    }                                                          \
                }                                                              \
            }                                                                  \
        }

    int i = gtid;
    for (; i + 3 * gsz < total4; i += 4 * gsz) {
        int4 a = __ldcs(ind4 + i);
        int4 b = __ldcs(ind4 + i + gsz);
        int4 c = __ldcs(ind4 + i + 2 * gsz);
        int4 d = __ldcs(ind4 + i + 3 * gsz);

        int ja = i << 2, jb = (i + gsz) << 2, jc = (i + 2 * gsz) << 2, jd = (i + 3 * gsz) << 2;
        EMIT(a.x, ja)     EMIT(a.y, ja + 1) EMIT(a.z, ja + 2) EMIT(a.w, ja + 3)
        EMIT(b.x, jb)     EMIT(b.y, jb + 1) EMIT(b.z, jb + 2) EMIT(b.w, jb + 3)
        EMIT(c.x, jc)     EMIT(c.y, jc + 1) EMIT(c.z, jc + 2) EMIT(c.w, jc + 3)
        EMIT(d.x, jd)     EMIT(d.y, jd + 1) EMIT(d.z, jd + 2) EMIT(d.w, jd + 3)
    }
    for (; i < total4; i += gsz) {
        int4 a = __ldcs(ind4 + i);
        int j = i << 2;
        EMIT(a.x, j) EMIT(a.y, j + 1) EMIT(a.z, j + 2) EMIT(a.w, j + 3)
    }
    int jt = (total4 << 2) + gtid;
    if (jt < nnz) {
        int e = indice[jt];
        EMIT(e, jt)
    }
    #undef EMIT

    // ---- per-CTA resolve of staged hits (parallel binary searches) ----
    __syncthreads();
    int nh = sc_cnt; if (nh > STAGE_CAP) nh = STAGE_CAP;
    for (int t = threadIdx.x; t < nh; t += 1024) {
        int j = sc_pos[t];
        int lo = 0, hi = n_docs;
        while (lo < hi) {
            int mid = (lo + hi + 1) >> 1;
            if (crow[mid] <= j) lo = mid; else hi = mid - 1;
        }
        float old = atomicAdd(&g_scores[lo], sc_val[t]);
        if (old == 0.0f) {
            int p = atomicAdd(&cd_cnt, 1);
            if (p < STAGE_CAP) cd_doc[p] = lo;
            else {
                int gp = atomicAdd(&g_ncand, 1);
                if (gp < CAND_CAP) g_cand_doc[gp] = lo;
            }
        }
    }

    // ---- flush candidates: ONE global atomic per CTA ----
    __syncthreads();
    if (threadIdx.x == 0) {
        int c = cd_cnt; if (c > STAGE_CAP) c = STAGE_CAP;
        int base = atomicAdd(&g_ncand, c);
        if (base + c > CAND_CAP) c = (base < CAND_CAP) ? (CAND_CAP - base) : 0;
        cd_base = base; cd_flush = c;
    }
    __syncthreads();
    for (int t = threadIdx.x; t < cd_flush; t += 1024)
        g_cand_doc[cd_base + t] = cd_doc[t];

    // ---- last-finishing CTA resolves the (rare) overflow spill ----
    __threadfence();
    if (threadIdx.x == 0)
        s_last = (atomicAdd(&g_done, 1) == gridDim.x - 1) ? 1 : 0;
    __syncthreads();
    if (s_last) {
        __threadfence();   // acquire side: see all spill writes
        int no = g_novf; if (no > OVF_CAP) no = OVF_CAP;
        for (int t = threadIdx.x; t < no; t += 1024) {
            int j = g_ovf_pos[t];
            int lo = 0, hi = n_docs;
            while (lo < hi) {
                int mid = (lo + hi + 1) >> 1;
                if (crow[mid] <= j) lo = mid; else hi = mid - 1;
            }
            float old = atomicAdd(&g_scores[lo], g_ovf_val[t]);
            if (old == 0.0f) {
                int gp = atomicAdd(&g_ncand, 1);
                if (gp < CAND_CAP) g_cand_doc[gp] = lo;
            }
        }
    }
}

// ---------------------------------------------------------------------------
// top-k helpers (static register indexing only)
// ---------------------------------------------------------------------------
__device__ __forceinline__ void insert10(float* lv, int* li, float s, int d) {
    if (s > lv[TOPK - 1] || (s == lv[TOPK - 1] && d < li[TOPK - 1])) {
        lv[TOPK - 1] = s; li[TOPK - 1] = d;
        #pragma unroll
        for (int k = TOPK - 1; k > 0; k--) {
            bool sw = (lv[k] > lv[k - 1]) ||
                      (lv[k] == lv[k - 1] && li[k] < li[k - 1]);
            if (sw) {
                float tv = lv[k]; lv[k] = lv[k - 1]; lv[k - 1] = tv;
                int   ti = li[k]; li[k] = li[k - 1]; li[k - 1] = ti;
            }
        }
    }
}

__device__ __forceinline__ void warp_merge10(float* lv, int* li,
                                             float* out_v, int* out_i) {
    int lane = threadIdx.x & 31;
    #pragma unroll
    for (int r = 0; r < TOPK; r++) {
        float bv = lv[0]; int bi = li[0]; int bl = lane;
        #pragma unroll
        for (int off = 16; off; off >>= 1) {
            float ov = __shfl_down_sync(0xffffffffu, bv, off);
            int   oi = __shfl_down_sync(0xffffffffu, bi, off);
            int   ol = __shfl_down_sync(0xffffffffu, bl, off);
            if (ov > bv || (ov == bv && oi < bi)) { bv = ov; bi = oi; bl = ol; }
        }
        bl = __shfl_sync(0xffffffffu, bl, 0);
        float wv = __shfl_sync(0xffffffffu, bv, 0);
        int   wi = __shfl_sync(0xffffffffu, bi, 0);
        if (lane == bl) {
            #pragma unroll
            for (int k = 0; k < TOPK - 1; k++) { lv[k] = lv[k + 1]; li[k] = li[k + 1]; }
            lv[TOPK - 1] = -FLT_MAX; li[TOPK - 1] = INT_MAX;
        }
        if (lane == 0) { out_v[r] = wv; out_i[r] = wi; }
    }
}

__device__ __forceinline__ void block_merge10(const float* sv, const int* si,
                                              int nwarp, float* out_v, int* out_i) {
    int lane = threadIdx.x & 31;
    float lv[TOPK]; int li[TOPK];
    #pragma unroll
    for (int k = 0; k < TOPK; k++) {
        if (lane < nwarp) { lv[k] = sv[lane * TOPK + k]; li[k] = si[lane * TOPK + k]; }
        else              { lv[k] = -FLT_MAX;            li[k] = INT_MAX;            }
    }
    warp_merge10(lv, li, out_v, out_i);
}

// ---------------------------------------------------------------------------
// top-k pass 1: scan candidates (batched gathers, MLP=4) AND zero each
// candidate score after reading it (fused cleanup -> restores invariant)
// ---------------------------------------------------------------------------
__global__ void __launch_bounds__(256)
topk1_kernel() {
    float lv[TOPK]; int li[TOPK];
    #pragma unroll
    for (int k = 0; k < TOPK; k++) { lv[k] = -FLT_MAX; li[k] = INT_MAX; }

    int nc = g_ncand;
    if (nc > CAND_CAP) nc = CAND_CAP;
    int gtid = blockIdx.x * blockDim.x + threadIdx.x;
    int gsz  = gridDim.x * blockDim.x;

    int t = gtid;
    for (; t + 3 * gsz < nc; t += 4 * gsz) {
        int d0 = g_cand_doc[t];
        int d1 = g_cand_doc[t + gsz];
        int d2 = g_cand_doc[t + 2 * gsz];
        int d3 = g_cand_doc[t + 3 * gsz];
        float s0 = g_scores[d0];
        float s1 = g_scores[d1];
        float s2 = g_scores[d2];
        float s3 = g_scores[d3];
        g_scores[d0] = 0.0f;
        g_scores[d1] = 0.0f;
        g_scores[d2] = 0.0f;
        g_scores[d3] = 0.0f;
        insert10(lv, li, s0, d0);
        insert10(lv, li, s1, d1);
        insert10(lv, li, s2, d2);
        insert10(lv, li, s3, d3);
    }
    for (; t < nc; t += gsz) {
        int d = g_cand_doc[t];
        float s = g_scores[d];
        g_scores[d] = 0.0f;
        insert10(lv, li, s, d);
    }

    __shared__ float sv[8 * TOPK];
    __shared__ int   si[8 * TOPK];
    int wid = threadIdx.x >> 5;
    warp_merge10(lv, li, sv + wid * TOPK, si + wid * TOPK);
    __syncthreads();
    if (wid == 0)
        block_merge10(sv, si, 8, g_blk_v + blockIdx.x * TOPK,
                      g_blk_i + blockIdx.x * TOPK);
}

// ---------------------------------------------------------------------------
// top-k pass 2: merge NB1*TOPK block winners, write output, reset counters
// out layout: [TOPK values][TOPK indices-as-float]
// ---------------------------------------------------------------------------
__global__ void __launch_bounds__(256)
topk2_kernel(float* __restrict__ out, int out_size) {
    const int NC = NB1 * TOPK;
    float lv[TOPK]; int li[TOPK];
    #pragma unroll
    for (int k = 0; k < TOPK; k++) { lv[k] = -FLT_MAX; li[k] = INT_MAX; }

    for (int p = threadIdx.x; p < NC; p += 256)
        insert10(lv, li, g_blk_v[p], g_blk_i[p]);

    __shared__ float sv[8 * TOPK];
    __shared__ int   si[8 * TOPK];
    __shared__ float fv[TOPK];
    __shared__ int   fi[TOPK];
    int wid = threadIdx.x >> 5;
    warp_merge10(lv, li, sv + wid * TOPK, si + wid * TOPK);
    __syncthreads();
    if (wid == 0) block_merge10(sv, si, 8, fv, fi);
    __syncthreads();

    if (threadIdx.x < TOPK) {
        int k = threadIdx.x;
        if (k < out_size) out[k] = fv[k];
        if (TOPK + k < out_size) out[TOPK + k] = (float)fi[k];
    }
    if (threadIdx.x == 0) {   // reset all counters for next graph replay
        g_ncand = 0;
        g_novf = 0;
        g_done = 0;
    }
}

// ---------------------------------------------------------------------------
// kernel_launch
// Inputs: q_indices(i32,32) q_values(f32,32) crow(i32,N+1) indice(i32,nnz)
//         values(f32,nnz) [top_k]
// ---------------------------------------------------------------------------
extern "C" void kernel_launch(void* const* d_in, const int* in_sizes, int n_in,
                              void* d_out, int out_size) {
    const int*   qidx   = (const int*)d_in[0];
    const float* qval   = (const float*)d_in[1];
    const int*   crow   = (const int*)d_in[2];
    const int*   indice = (const int*)d_in[3];
    const float* values = (const float*)d_in[4];

    int qn     = in_sizes[0];
    int n_docs = in_sizes[2] - 1;
    int nnz    = in_sizes[3];

    const int SMEM_Q = VOCAB * (int)sizeof(float);
    cudaFuncSetAttribute(score_kernel, cudaFuncAttributeMaxDynamicSharedMemorySize, SMEM_Q);

    score_kernel<<<148, 1024, SMEM_Q>>>(qidx, qval, qn, indice, values,
                                        crow, n_docs, nnz);
    topk1_kernel<<<NB1, 256>>>();
    topk2_kernel<<<1, 256>>>((float*)d_out, out_size);
}